// round 9
// baseline (speedup 1.0000x reference)
#include <cuda_runtime.h>
#include <cuda_fp16.h>
#include <mma.h>
#include <cstdint>

using namespace nvcuda;

#define D_MODEL 2048
#define NUM_EXPERTS 64
#define M_TILE 128
#define KC 32
#define KSPLIT 2
#define KHALF (D_MODEL / KSPLIT)       // 1024
#define T_CHUNKS (KHALF / KC)          // 32
#define NTHREADS 256
#define AS 40
#define WS 40
#define A_ELTS (M_TILE * AS)
#define B_ELTS (NUM_EXPERTS * WS)
#define SBUF_ELTS (2 * A_ELTS + 2 * B_ELTS)
#define SMEM_BYTES (2 * SBUF_ELTS * 2)   // 61440 B
#define LSTRIDE 72
#define N_ROWS 32768

// W pre-packed chunk-contiguous: [chunk][lev][e][32 halfs]
__device__ __align__(16) __half g_wp[2 * NUM_EXPERTS * D_MODEL];
// fp32 partial logits: [kh][row][expert]
__device__ __align__(16) float g_partial[KSPLIT * N_ROWS * NUM_EXPERTS];

__global__ void prep_w(const float* __restrict__ w) {
    int i = (blockIdx.x * blockDim.x + threadIdx.x) * 4;
    float4 v = *reinterpret_cast<const float4*>(w + i);
    float a[4] = {v.x, v.y, v.z, v.w};
    __half h0[4], h1[4];
#pragma unroll
    for (int j = 0; j < 4; j++) {
        __half t0 = __float2half_rn(a[j]);
        h0[j] = t0;
        h1[j] = __float2half_rn(a[j] - __half2float(t0));
    }
    const int e = i / D_MODEL;
    const int k = i % D_MODEL;
    const int c = k >> 5;
    const int kk = k & 31;
    __half* d0 = g_wp + ((size_t)(c * 2 + 0) * 64 + e) * 32 + kk;
    __half* d1 = g_wp + ((size_t)(c * 2 + 1) * 64 + e) * 32 + kk;
    *reinterpret_cast<uint2*>(d0) = *reinterpret_cast<uint2*>(h0);
    *reinterpret_cast<uint2*>(d1) = *reinterpret_cast<uint2*>(h1);
}

__global__ void __launch_bounds__(NTHREADS, 3) router_gemm(
    const float* __restrict__ x)
{
    extern __shared__ __align__(16) __half smem[];

    const int tid = threadIdx.x;
    const int wid = tid >> 5;
    const int wm = wid & 3;
    const int wn = wid >> 2;
    const int kh = blockIdx.x & 1;               // K half
    const int mt_idx = blockIdx.x >> 1;          // m tile
    const long long row0 = (long long)mt_idx * M_TILE;

    const int xr  = tid >> 3;
    const int xc4 = (tid & 7) * 4;
    const int we  = tid >> 2;            // expert 0..63
    const int wq  = (tid & 3) * 8;       // k offset (halfs)

    const float* xb = x + row0 * D_MODEL + kh * KHALF;

    wmma::fragment<wmma::accumulator, 16, 16, 16, float> acc[2][2];
#pragma unroll
    for (int mt = 0; mt < 2; mt++)
#pragma unroll
        for (int nt = 0; nt < 2; nt++) wmma::fill_fragment(acc[mt][nt], 0.0f);

    float4 xv[4];
    uint4 wv[2];

    auto loadg = [&](int c) {
        const int k0 = c * KC;
#pragma unroll
        for (int i = 0; i < 4; i++)
            xv[i] = *reinterpret_cast<const float4*>(
                xb + (long long)(xr + 32 * i) * D_MODEL + k0 + xc4);
        const __half* wbase = g_wp + (size_t)(kh * T_CHUNKS + c) * 2 * NUM_EXPERTS * KC;
        wv[0] = *reinterpret_cast<const uint4*>(wbase + tid * 8);
        wv[1] = *reinterpret_cast<const uint4*>(wbase + 2048 + tid * 8);
    };

    auto stores = [&](int buf) {
        __half* A0 = smem + buf * SBUF_ELTS;
        __half* A1 = A0 + A_ELTS;
        __half* B0 = A0 + 2 * A_ELTS;
        __half* B1 = B0 + B_ELTS;
#pragma unroll
        for (int i = 0; i < 4; i++) {
            float a0 = xv[i].x, a1 = xv[i].y, a2 = xv[i].z, a3 = xv[i].w;
            __half2 h0a = __floats2half2_rn(a0, a1);
            __half2 h0b = __floats2half2_rn(a2, a3);
            float r0 = a0 - __half2float(h0a.x);
            float r1 = a1 - __half2float(h0a.y);
            float r2 = a2 - __half2float(h0b.x);
            float r3 = a3 - __half2float(h0b.y);
            __half2 h1a = __floats2half2_rn(r0, r1);
            __half2 h1b = __floats2half2_rn(r2, r3);

            const int o = (xr + 32 * i) * AS + xc4;
            *reinterpret_cast<uint2*>(A0 + o) =
                make_uint2(*reinterpret_cast<uint32_t*>(&h0a), *reinterpret_cast<uint32_t*>(&h0b));
            *reinterpret_cast<uint2*>(A1 + o) =
                make_uint2(*reinterpret_cast<uint32_t*>(&h1a), *reinterpret_cast<uint32_t*>(&h1b));
        }
        const int bo = we * WS + wq;
        *reinterpret_cast<uint4*>((smem + buf * SBUF_ELTS + 2 * A_ELTS) + bo) = wv[0];
        *reinterpret_cast<uint4*>((smem + buf * SBUF_ELTS + 2 * A_ELTS + B_ELTS) + bo) = wv[1];
    };

    auto compute = [&](int buf) {
        const __half* A0 = smem + buf * SBUF_ELTS;
        const __half* A1 = A0 + A_ELTS;
        const __half* B0 = A0 + 2 * A_ELTS;
        const __half* B1 = B0 + B_ELTS;
#pragma unroll
        for (int ks = 0; ks < KC; ks += 16) {
            wmma::fragment<wmma::matrix_a, 16, 16, 16, __half, wmma::row_major> a0f[2], a1f[2];
            wmma::fragment<wmma::matrix_b, 16, 16, 16, __half, wmma::col_major> b0f[2], b1f[2];
#pragma unroll
            for (int mt = 0; mt < 2; mt++) {
                const int ro = (32 * wm + 16 * mt) * AS + ks;
                wmma::load_matrix_sync(a0f[mt], A0 + ro, AS);
                wmma::load_matrix_sync(a1f[mt], A1 + ro, AS);
            }
#pragma unroll
            for (int nt = 0; nt < 2; nt++) {
                const int co = (32 * wn + 16 * nt) * WS + ks;
                wmma::load_matrix_sync(b0f[nt], B0 + co, WS);
                wmma::load_matrix_sync(b1f[nt], B1 + co, WS);
            }
#pragma unroll
            for (int mt = 0; mt < 2; mt++)
#pragma unroll
                for (int nt = 0; nt < 2; nt++)
                    wmma::mma_sync(acc[mt][nt], a0f[mt], b0f[nt], acc[mt][nt]);
#pragma unroll
            for (int mt = 0; mt < 2; mt++)
#pragma unroll
                for (int nt = 0; nt < 2; nt++)
                    wmma::mma_sync(acc[mt][nt], a0f[mt], b1f[nt], acc[mt][nt]);
#pragma unroll
            for (int mt = 0; mt < 2; mt++)
#pragma unroll
                for (int nt = 0; nt < 2; nt++)
                    wmma::mma_sync(acc[mt][nt], a1f[mt], b0f[nt], acc[mt][nt]);
        }
    };

    loadg(0);
    stores(0);
    __syncthreads();

#pragma unroll 1
    for (int c = 0; c < T_CHUNKS; ++c) {
        if (c + 1 < T_CHUNKS) loadg(c + 1);
        compute(c & 1);
        if (c + 1 < T_CHUNKS) stores((c + 1) & 1);
        __syncthreads();
    }

    // ---- write partial logits ----
    float* logits = reinterpret_cast<float*>(smem);
#pragma unroll
    for (int mt = 0; mt < 2; mt++)
#pragma unroll
        for (int nt = 0; nt < 2; nt++)
            wmma::store_matrix_sync(
                logits + (32 * wm + 16 * mt) * LSTRIDE + 32 * wn + 16 * nt,
                acc[mt][nt], LSTRIDE, wmma::mem_row_major);
    __syncthreads();

    {
        const int r2 = tid >> 1;            // row 0..127
        const int cb = (tid & 1) * 32;      // col base
        float* dst = g_partial + ((size_t)kh * N_ROWS + row0 + r2) * NUM_EXPERTS + cb;
        const float* src = logits + r2 * LSTRIDE + cb;
#pragma unroll
        for (int j = 0; j < 8; j++)
            *reinterpret_cast<float4*>(dst + 4 * j) = *reinterpret_cast<const float4*>(src + 4 * j);
    }
}

__global__ void __launch_bounds__(256) router_top2(
    const float* __restrict__ bias,
    float* __restrict__ out,
    int n_rows)
{
    const int r = blockIdx.x * blockDim.x + threadIdx.x;
    const float* p0 = g_partial + (size_t)r * NUM_EXPERTS;
    const float* p1 = g_partial + ((size_t)n_rows + r) * NUM_EXPERTS;

    float lg[NUM_EXPERTS];
#pragma unroll
    for (int j = 0; j < NUM_EXPERTS / 4; j++) {
        float4 a = *reinterpret_cast<const float4*>(p0 + 4 * j);
        float4 b = *reinterpret_cast<const float4*>(p1 + 4 * j);
        lg[4 * j + 0] = a.x + b.x + __ldg(&bias[4 * j + 0]);
        lg[4 * j + 1] = a.y + b.y + __ldg(&bias[4 * j + 1]);
        lg[4 * j + 2] = a.z + b.z + __ldg(&bias[4 * j + 2]);
        lg[4 * j + 3] = a.w + b.w + __ldg(&bias[4 * j + 3]);
    }

    float v0 = -3.0e38f, v1 = -3.0e38f;
    int i0 = 0, i1 = 0;
#pragma unroll
    for (int e = 0; e < NUM_EXPERTS; e++) {
        float l = lg[e];
        if (l > v0) { v1 = v0; i1 = i0; v0 = l; i0 = e; }
        else if (l > v1) { v1 = l; i1 = e; }
    }
    float Z = 0.0f;
#pragma unroll
    for (int e = 0; e < NUM_EXPERTS; e++)
        Z += __expf(lg[e] - v0);

    float q0 = 1.0f / Z;
    float q1 = __expf(v1 - v0) / Z;
    float s = q0 + q1 + 1e-8f;
    out[(size_t)r * 2 + 0] = q0 / s;
    out[(size_t)r * 2 + 1] = q1 / s;
    float* ido = out + (size_t)n_rows * 2;
    ido[(size_t)r * 2 + 0] = (float)i0;
    ido[(size_t)r * 2 + 1] = (float)i1;
}

extern "C" void kernel_launch(void* const* d_in, const int* in_sizes, int n_in,
                              void* d_out, int out_size) {
    const float* x    = (const float*)d_in[0];
    const float* gw   = (const float*)d_in[1];
    const float* bias = (const float*)d_in[2];
    float* out = (float*)d_out;
    int n_rows = in_sizes[0] / D_MODEL;   // 32768

    cudaFuncSetAttribute(router_gemm, cudaFuncAttributeMaxDynamicSharedMemorySize, SMEM_BYTES);

    prep_w<<<(NUM_EXPERTS * D_MODEL / 4) / 256, 256>>>(gw);
    router_gemm<<<(n_rows / M_TILE) * KSPLIT, NTHREADS, SMEM_BYTES>>>(x);
    router_top2<<<n_rows / 256, 256>>>(bias, out, n_rows);
}

// round 10
// speedup vs baseline: 1.5879x; 1.5879x over previous
#include <cuda_runtime.h>
#include <cuda_fp16.h>
#include <cstdint>

#define D_MODEL 2048
#define NUM_EXPERTS 64
#define M_TILE 128
#define KC 32
#define T_CHUNKS (D_MODEL / KC)    // 64
#define NTHREADS 256
#define AS 40                       // A row stride (halfs) = 80B, ldmatrix conflict-free
#define A_LEV_BYTES (M_TILE * AS * 2)       // 10240
#define STAGE_BYTES (2 * A_LEV_BYTES)       // 20480
#define SMEM_BYTES (2 * STAGE_BYTES)        // 40960 (logits 36864 fits)
#define LSTRIDE 72

// W pre-packed in m16n8k16 B-fragment lane order:
// index = ((((c*2 + wn)*2 + ks)*2 + lev)*4 + nf)*32 + lane   (uint2 each)
//   n = wn*32 + nf*8 + lane/4 ; k0 = c*32 + ks*16 + (lane&3)*2
//   .x = half2(w[n][k0], w[n][k0+1]) ; .y = half2(w[n][k0+8], w[n][k0+9])
__device__ __align__(16) uint2 g_wf[T_CHUNKS * 2 * 2 * 2 * 4 * 32];

__global__ void prep_w(const float* __restrict__ w) {
    const int idx = blockIdx.x * blockDim.x + threadIdx.x;   // 65536 total
    const int lane = idx & 31;
    const int nf   = (idx >> 5) & 3;
    const int lev  = (idx >> 7) & 1;
    const int ks   = (idx >> 8) & 1;
    const int wn   = (idx >> 9) & 1;
    const int c    = idx >> 10;

    const int n  = wn * 32 + nf * 8 + (lane >> 2);
    const int k0 = c * 32 + ks * 16 + (lane & 3) * 2;

    const float* row = w + (size_t)n * D_MODEL;
    float2 va = *reinterpret_cast<const float2*>(row + k0);
    float2 vb = *reinterpret_cast<const float2*>(row + k0 + 8);

    float v[4] = {va.x, va.y, vb.x, vb.y};
    __half h[4];
#pragma unroll
    for (int j = 0; j < 4; j++) {
        __half h0 = __float2half_rn(v[j]);
        h[j] = lev ? __float2half_rn(v[j] - __half2float(h0)) : h0;
    }
    __half2 lo = __halves2half2(h[0], h[1]);
    __half2 hi = __halves2half2(h[2], h[3]);
    uint2 o;
    o.x = *reinterpret_cast<uint32_t*>(&lo);
    o.y = *reinterpret_cast<uint32_t*>(&hi);
    g_wf[idx] = o;
}

__device__ __forceinline__ uint32_t smem_u32(const void* p) {
    uint32_t a;
    asm("{ .reg .u64 t; cvta.to.shared.u64 t, %1; cvt.u32.u64 %0, t; }" : "=r"(a) : "l"(p));
    return a;
}
__device__ __forceinline__ void ldmatrix_x4(uint32_t* r, uint32_t addr) {
    asm volatile("ldmatrix.sync.aligned.m8n8.x4.shared.b16 {%0,%1,%2,%3}, [%4];"
                 : "=r"(r[0]), "=r"(r[1]), "=r"(r[2]), "=r"(r[3]) : "r"(addr));
}
__device__ __forceinline__ void mma16816(float* d, const uint32_t* a, uint2 b) {
    asm volatile(
        "mma.sync.aligned.m16n8k16.row.col.f32.f16.f16.f32 "
        "{%0,%1,%2,%3}, {%4,%5,%6,%7}, {%8,%9}, {%0,%1,%2,%3};"
        : "+f"(d[0]), "+f"(d[1]), "+f"(d[2]), "+f"(d[3])
        : "r"(a[0]), "r"(a[1]), "r"(a[2]), "r"(a[3]), "r"(b.x), "r"(b.y));
}

__global__ void __launch_bounds__(NTHREADS, 2) router_mma(
    const float* __restrict__ x,
    const float* __restrict__ bias,
    float* __restrict__ out,
    int n_rows)
{
    extern __shared__ __align__(16) char smem[];
    const uint32_t sbase = smem_u32(smem);

    const int tid = threadIdx.x;
    const int wid = tid >> 5;
    const int lane = tid & 31;
    const int wm = wid & 3;        // warp m-group: rows 32*wm..+31
    const int wn = wid >> 2;       // warp n-group: experts 32*wn..+31
    const long long row0 = (long long)blockIdx.x * M_TILE;

    // x loader: 8 lanes cover one 128B line
    const int xr  = tid >> 3;
    const int xc4 = (tid & 7) * 4;

    const float* xb = x + row0 * D_MODEL;

    // acc[mt][nf][4] : m16n8 tile (rows wm*32+mt*16.., cols wn*32+nf*8..)
    float acc[2][4][4];
#pragma unroll
    for (int mt = 0; mt < 2; mt++)
#pragma unroll
        for (int nf = 0; nf < 4; nf++)
#pragma unroll
            for (int j = 0; j < 4; j++) acc[mt][nf][j] = 0.0f;

    float4 xv[4];

    auto loadg = [&](int c) {
        const int k0 = c * KC;
#pragma unroll
        for (int i = 0; i < 4; i++)
            xv[i] = *reinterpret_cast<const float4*>(
                xb + (long long)(xr + 32 * i) * D_MODEL + k0 + xc4);
    };

    auto stores = [&](int buf) {
        char* A0 = smem + buf * STAGE_BYTES;
        char* A1 = A0 + A_LEV_BYTES;
#pragma unroll
        for (int i = 0; i < 4; i++) {
            float a0 = xv[i].x, a1 = xv[i].y, a2 = xv[i].z, a3 = xv[i].w;
            __half2 h0a = __floats2half2_rn(a0, a1);
            __half2 h0b = __floats2half2_rn(a2, a3);
            float r0 = a0 - __half2float(h0a.x);
            float r1 = a1 - __half2float(h0a.y);
            float r2 = a2 - __half2float(h0b.x);
            float r3 = a3 - __half2float(h0b.y);
            __half2 h1a = __floats2half2_rn(r0, r1);
            __half2 h1b = __floats2half2_rn(r2, r3);

            const int o = ((xr + 32 * i) * AS + xc4) * 2;   // bytes
            *reinterpret_cast<uint2*>(A0 + o) =
                make_uint2(*reinterpret_cast<uint32_t*>(&h0a), *reinterpret_cast<uint32_t*>(&h0b));
            *reinterpret_cast<uint2*>(A1 + o) =
                make_uint2(*reinterpret_cast<uint32_t*>(&h1a), *reinterpret_cast<uint32_t*>(&h1b));
        }
    };

    // ldmatrix per-lane address pieces (constant across chunks except buf/ks/lev/mt)
    const int lrow = ((lane >> 3) & 1) * 8 + (lane & 7);  // row within m16 tile (t&1)*8 + r
    const int lkof = (lane >> 4) * 8;                     // k offset within k16 tile (t>>1)*8

    auto compute = [&](int c, int buf) {
        const uint32_t Ab = sbase + buf * STAGE_BYTES;
        const uint2* Wf = g_wf + ((size_t)(c * 2 + wn)) * (2 * 2 * 4 * 32);
#pragma unroll
        for (int ks = 0; ks < 2; ks++) {
            // B frags first (gmem, L2-resident; no barrier dependency)
            uint2 b[2][4];
#pragma unroll
            for (int lev = 0; lev < 2; lev++)
#pragma unroll
                for (int nf = 0; nf < 4; nf++)
                    b[lev][nf] = Wf[((ks * 2 + lev) * 4 + nf) * 32 + lane];

            // A frags via ldmatrix
            uint32_t a[2][2][4];
#pragma unroll
            for (int mt = 0; mt < 2; mt++)
#pragma unroll
                for (int lev = 0; lev < 2; lev++) {
                    uint32_t addr = Ab + lev * A_LEV_BYTES +
                        ((wm * 32 + mt * 16 + lrow) * AS + ks * 16 + lkof) * 2;
                    ldmatrix_x4(a[mt][lev], addr);
                }

            // 3 products, product-major (dep distance 8)
#pragma unroll
            for (int mt = 0; mt < 2; mt++)
#pragma unroll
                for (int nf = 0; nf < 4; nf++)
                    mma16816(acc[mt][nf], a[mt][0], b[0][nf]);
#pragma unroll
            for (int mt = 0; mt < 2; mt++)
#pragma unroll
                for (int nf = 0; nf < 4; nf++)
                    mma16816(acc[mt][nf], a[mt][0], b[1][nf]);
#pragma unroll
            for (int mt = 0; mt < 2; mt++)
#pragma unroll
                for (int nf = 0; nf < 4; nf++)
                    mma16816(acc[mt][nf], a[mt][1], b[0][nf]);
        }
    };

    // ---- double-buffered main loop (R6 structure) ----
    loadg(0);
    stores(0);
    __syncthreads();

#pragma unroll 1
    for (int c = 0; c < T_CHUNKS; ++c) {
        if (c + 1 < T_CHUNKS) loadg(c + 1);
        compute(c, c & 1);
        if (c + 1 < T_CHUNKS) stores((c + 1) & 1);
        __syncthreads();
    }

    // ---- epilogue: scatter acc to logits smem ----
    float* logits = reinterpret_cast<float*>(smem);
#pragma unroll
    for (int mt = 0; mt < 2; mt++)
#pragma unroll
        for (int nf = 0; nf < 4; nf++) {
            const int r = wm * 32 + mt * 16 + (lane >> 2);
            const int col = wn * 32 + nf * 8 + (lane & 3) * 2;
            *reinterpret_cast<float2*>(logits + r * LSTRIDE + col) =
                make_float2(acc[mt][nf][0], acc[mt][nf][1]);
            *reinterpret_cast<float2*>(logits + (r + 8) * LSTRIDE + col) =
                make_float2(acc[mt][nf][2], acc[mt][nf][3]);
        }
    __syncthreads();

    if (tid < M_TILE) {
        const int r = tid;
        const float* lrw = logits + r * LSTRIDE;
        float v0 = -3.0e38f, v1 = -3.0e38f;
        int i0 = 0, i1 = 0;
#pragma unroll
        for (int e = 0; e < NUM_EXPERTS; e++) {
            float l = lrw[e] + __ldg(&bias[e]);
            if (l > v0) { v1 = v0; i1 = i0; v0 = l; i0 = e; }
            else if (l > v1) { v1 = l; i1 = e; }
        }
        float Z = 0.0f;
#pragma unroll
        for (int e = 0; e < NUM_EXPERTS; e++) {
            float l = lrw[e] + __ldg(&bias[e]);
            Z += __expf(l - v0);
        }
        float q0 = 1.0f / Z;
        float q1 = __expf(v1 - v0) / Z;
        float s = q0 + q1 + 1e-8f;
        long long gr = row0 + r;
        out[gr * 2 + 0] = q0 / s;
        out[gr * 2 + 1] = q1 / s;
        float* ido = out + (long long)n_rows * 2;
        ido[gr * 2 + 0] = (float)i0;
        ido[gr * 2 + 1] = (float)i1;
    }
}

extern "C" void kernel_launch(void* const* d_in, const int* in_sizes, int n_in,
                              void* d_out, int out_size) {
    const float* x    = (const float*)d_in[0];
    const float* gw   = (const float*)d_in[1];
    const float* bias = (const float*)d_in[2];
    float* out = (float*)d_out;
    int n_rows = in_sizes[0] / D_MODEL;   // 32768

    cudaFuncSetAttribute(router_mma, cudaFuncAttributeMaxDynamicSharedMemorySize, SMEM_BYTES);

    prep_w<<<(T_CHUNKS * 2 * 2 * 2 * 4 * 32) / 256, 256>>>(gw);
    router_mma<<<n_rows / M_TILE, NTHREADS, SMEM_BYTES>>>(x, bias, out, n_rows);
}